// round 14
// baseline (speedup 1.0000x reference)
#include <cuda_runtime.h>
#include <cuda_bf16.h>
#include <cuda_fp16.h>
#include <math.h>
#include <stdint.h>

#define Vv 50257
#define Hh 1024
#define Ll 10
#define Bb 256

// -------- scratch (no allocations allowed; __device__ globals) ----------
__device__ float g_xin[Bb * 2 * Hh];          // concat(embedded, attn_applied)
__device__ float g_x[Bb * Hh];                // combine accum (pre-relu, atomic)
__device__ float g_gi[Bb * 3 * Hh];
__device__ float g_gh[Bb * 3 * Hh];
__device__ __nv_bfloat16 g_hnbf[Bb * Hh];     // h_new in bf16 for the big GEMM
__device__ float g_expsum[Bb];                // per-row sum(exp(logit))

// -------- helpers ----------
__device__ __forceinline__ unsigned pack_bf2(float a, float b) {
    __nv_bfloat162 t = __floats2bfloat162_rn(a, b);
    return *reinterpret_cast<unsigned*>(&t);
}

__device__ __forceinline__ unsigned pack_h2(float a, float b) {
    __half2 t = __floats2half2_rn(a, b);
    return *reinterpret_cast<unsigned*>(&t);
}

__device__ __forceinline__ void mma_bf16(float* d,
    unsigned a0, unsigned a1, unsigned a2, unsigned a3,
    unsigned b0, unsigned b1) {
    asm volatile(
        "mma.sync.aligned.m16n8k16.row.col.f32.bf16.bf16.f32 "
        "{%0,%1,%2,%3}, {%4,%5,%6,%7}, {%8,%9}, {%0,%1,%2,%3};"
        : "+f"(d[0]), "+f"(d[1]), "+f"(d[2]), "+f"(d[3])
        : "r"(a0), "r"(a1), "r"(a2), "r"(a3), "r"(b0), "r"(b1));
}

__device__ __forceinline__ void mma_f16(float* d,
    unsigned a0, unsigned a1, unsigned a2, unsigned a3,
    unsigned b0, unsigned b1) {
    asm volatile(
        "mma.sync.aligned.m16n8k16.row.col.f32.f16.f16.f32 "
        "{%0,%1,%2,%3}, {%4,%5,%6,%7}, {%8,%9}, {%0,%1,%2,%3};"
        : "+f"(d[0]), "+f"(d[1]), "+f"(d[2]), "+f"(d[3])
        : "r"(a0), "r"(a1), "r"(a2), "r"(a3), "r"(b0), "r"(b1));
}

__device__ __forceinline__ uint32_t smem_u32(const void* p) {
    uint32_t a;
    asm("{ .reg .u64 t; cvta.to.shared.u64 t, %1; cvt.u32.u64 %0, t; }" : "=r"(a) : "l"(p));
    return a;
}

__device__ __forceinline__ void sts128(uint32_t addr, uint4 v) {
    asm volatile("st.shared.v4.b32 [%0], {%1,%2,%3,%4};"
                 :: "r"(addr), "r"(v.x), "r"(v.y), "r"(v.z), "r"(v.w) : "memory");
}

__device__ __forceinline__ void ldm_x4(unsigned* r, uint32_t addr) {
    asm volatile("ldmatrix.sync.aligned.m8n8.x4.shared.b16 {%0,%1,%2,%3}, [%4];"
                 : "=r"(r[0]), "=r"(r[1]), "=r"(r[2]), "=r"(r[3]) : "r"(addr));
}

#define CP_ASYNC16(dst, src) \
    asm volatile("cp.async.cg.shared.global [%0], [%1], 16;" :: "r"(dst), "l"(src))
#define CP_COMMIT() asm volatile("cp.async.commit_group;" ::: "memory")
#define CP_WAIT(n)  asm volatile("cp.async.wait_group %0;" :: "n"(n) : "memory")

// -------- K1: embedding gather + attention + zero combine accumulator -----
__global__ void attn_kernel(const int* __restrict__ tokens,
                            const float* __restrict__ hidden,
                            const float* __restrict__ enc,
                            const float* __restrict__ emb,
                            const float* __restrict__ attn_W,
                            const float* __restrict__ attn_b,
                            float* __restrict__ out) {
    int b = blockIdx.x, tid = threadIdx.x;
    int tok = tokens[b];
    for (int j = tid; j < Hh; j += 256) g_x[b * Hh + j] = 0.f;

    float part[Ll];
#pragma unroll
    for (int l = 0; l < Ll; l++) part[l] = 0.f;

    for (int k = tid; k < 2 * Hh; k += 256) {
        float v;
        if (k < Hh) { v = emb[(long)tok * Hh + k]; g_xin[b * 2 * Hh + k] = v; }
        else          v = hidden[b * Hh + k - Hh];
#pragma unroll
        for (int l = 0; l < Ll; l++) part[l] += v * attn_W[l * 2 * Hh + k];
    }
#pragma unroll
    for (int l = 0; l < Ll; l++)
#pragma unroll
        for (int o = 16; o; o >>= 1) part[l] += __shfl_xor_sync(0xffffffffu, part[l], o);

    __shared__ float ws[8][Ll];
    __shared__ float wsm[Ll];
    int wid = tid >> 5, lane = tid & 31;
    if (lane == 0)
        for (int l = 0; l < Ll; l++) ws[wid][l] = part[l];
    __syncthreads();
    if (tid == 0) {
        float lg[Ll]; float mx = -1e30f;
        for (int l = 0; l < Ll; l++) {
            float s = attn_b[l];
            for (int w = 0; w < 8; w++) s += ws[w][l];
            lg[l] = s; mx = fmaxf(mx, s);
        }
        float sum = 0.f;
        for (int l = 0; l < Ll; l++) { lg[l] = expf(lg[l] - mx); sum += lg[l]; }
        float inv = 1.f / sum;
        for (int l = 0; l < Ll; l++) wsm[l] = lg[l] * inv;
    }
    __syncthreads();
    if (tid < Ll) out[(long)Bb * Vv + Bb * Hh + b * Ll + tid] = wsm[tid];

    float w[Ll];
#pragma unroll
    for (int l = 0; l < Ll; l++) w[l] = wsm[l];
    for (int j = tid; j < Hh; j += 256) {
        float s = 0.f;
#pragma unroll
        for (int l = 0; l < Ll; l++) s += w[l] * enc[l * Hh + j];
        g_xin[b * 2 * Hh + Hh + j] = s;
    }
}

// ======== front GEMM: C = A @ W^T (+bias), fp16 A x fp16 W ================
// blockIdx.z < ksplit -> problem 0, K-slice z (atomicAdd when ksplit>1);
// blockIdx.z == ksplit -> problem 1 (independent, direct store).
// Per-problem N/K; CTAs with n0 >= N exit immediately.
#define F_ASTG 10240
#define F_WSTG 5120
#define F_STG  (F_ASTG + F_WSTG)

__global__ __launch_bounds__(256, 2) void gemm_front2(
    const float* __restrict__ A0, const float* __restrict__ W0,
    const float* __restrict__ b0, float* __restrict__ C0, int relu0,
    int N0, int K0,
    const float* __restrict__ A1, const float* __restrict__ W1,
    const float* __restrict__ b1, float* __restrict__ C1, int relu1,
    int N1, int K1,
    int ksplit) {
    __shared__ __align__(16) char smf[2 * F_STG];
    uint32_t base = smem_u32(smf);

    int prob, kz, atomic;
    if ((int)blockIdx.z < ksplit) { prob = 0; kz = blockIdx.z; atomic = (ksplit > 1); }
    else                          { prob = 1; kz = 0; atomic = 0; }
    const float* A    = prob ? A1 : A0;
    const float* W    = prob ? W1 : W0;
    const float* bias = prob ? b1 : b0;
    float*       C    = prob ? C1 : C0;
    const int relu_a  = prob ? relu1 : relu0;
    const int N       = prob ? N1 : N0;
    const int K       = prob ? K1 : K0;
    const int ks      = prob ? 1 : ksplit;

    const int n0 = blockIdx.x * 64;
    if (n0 >= N) return;
    const int m0 = blockIdx.y * 128;

    const int Kloc = K / ks;
    const int kbase = kz * Kloc;
    const int NS = Kloc >> 5;

    const int tid = threadIdx.x, wid = tid >> 5, lane = tid & 31;
    const int wM = wid & 1, wN = wid >> 1;
    const int g = lane >> 2, t = lane & 3;

    const int arow = tid >> 1, ahf = tid & 1;
    const int wrow = tid >> 2, wq = tid & 3;
    const float* asrc = A + (long)(m0 + arow) * K + kbase + ahf * 16;
    const float* wsrc = W + (long)(n0 + wrow) * K + kbase + wq * 8;

    float acc[4][2][4];
#pragma unroll
    for (int i = 0; i < 4; i++)
#pragma unroll
        for (int j = 0; j < 2; j++)
#pragma unroll
            for (int q = 0; q < 4; q++) acc[i][j][q] = 0.f;

    float ra[16], rw[8];

#define LDG_F(s)                                                          \
    {                                                                     \
        const float4* pa = reinterpret_cast<const float4*>(asrc + (s) * 32); \
        reinterpret_cast<float4*>(ra)[0] = pa[0];                         \
        reinterpret_cast<float4*>(ra)[1] = pa[1];                         \
        reinterpret_cast<float4*>(ra)[2] = pa[2];                         \
        reinterpret_cast<float4*>(ra)[3] = pa[3];                         \
        const float4* pw = reinterpret_cast<const float4*>(wsrc + (s) * 32); \
        reinterpret_cast<float4*>(rw)[0] = pw[0];                         \
        reinterpret_cast<float4*>(rw)[1] = pw[1];                         \
    }

#define RL(v) (relu_a ? fmaxf(v, 0.f) : (v))

#define STS_F(buf)                                                        \
    {                                                                     \
        uint32_t ab = base + (buf) * F_STG + arow * 80 + ahf * 32;        \
        uint4 u0, u1;                                                     \
        u0.x = pack_h2(RL(ra[0]),  RL(ra[1]));                            \
        u0.y = pack_h2(RL(ra[2]),  RL(ra[3]));                            \
        u0.z = pack_h2(RL(ra[4]),  RL(ra[5]));                            \
        u0.w = pack_h2(RL(ra[6]),  RL(ra[7]));                            \
        u1.x = pack_h2(RL(ra[8]),  RL(ra[9]));                            \
        u1.y = pack_h2(RL(ra[10]), RL(ra[11]));                           \
        u1.z = pack_h2(RL(ra[12]), RL(ra[13]));                           \
        u1.w = pack_h2(RL(ra[14]), RL(ra[15]));                           \
        sts128(ab, u0); sts128(ab + 16, u1);                              \
        uint32_t whb = base + (buf) * F_STG + F_ASTG + wrow * 80 + wq * 16; \
        uint4 h;                                                          \
        h.x = pack_h2(rw[0], rw[1]);                                      \
        h.y = pack_h2(rw[2], rw[3]);                                      \
        h.z = pack_h2(rw[4], rw[5]);                                      \
        h.w = pack_h2(rw[6], rw[7]);                                      \
        sts128(whb, h);                                                   \
    }

    LDG_F(0); STS_F(0);
    if (NS > 1) LDG_F(1);
    __syncthreads();

    const int l15 = lane & 15, l16o = (lane >> 4) * 16;
    for (int s = 0; s < NS; s++) {
        int buf = s & 1;
        uint32_t ab = base + buf * F_STG;
        uint32_t whb = ab + F_ASTG;
#pragma unroll
        for (int kf = 0; kf < 2; kf++) {
            unsigned a[4][4], bh[2][2], r[4];
#pragma unroll
            for (int mf = 0; mf < 4; mf++)
                ldm_x4(a[mf], ab + (wM * 64 + mf * 16 + l15) * 80 + kf * 32 + l16o);
            ldm_x4(r, whb + (wN * 16 + l15) * 80 + kf * 32 + l16o);
            bh[0][0] = r[0]; bh[0][1] = r[2]; bh[1][0] = r[1]; bh[1][1] = r[3];
#pragma unroll
            for (int mf = 0; mf < 4; mf++)
#pragma unroll
                for (int nf = 0; nf < 2; nf++)
                    mma_f16(acc[mf][nf], a[mf][0], a[mf][1], a[mf][2], a[mf][3],
                            bh[nf][0], bh[nf][1]);
        }
        if (s + 1 < NS) STS_F((s + 1) & 1);
        if (s + 2 < NS) LDG_F(s + 2);
        __syncthreads();
    }
#undef LDG_F
#undef STS_F
#undef RL

#pragma unroll
    for (int mf = 0; mf < 4; mf++)
#pragma unroll
        for (int nf = 0; nf < 2; nf++) {
            int row = m0 + wM * 64 + mf * 16 + g;
            int col = n0 + wN * 16 + nf * 8 + t * 2;
            float b0v = (kz == 0) ? bias[col] : 0.f;
            float b1v = (kz == 0) ? bias[col + 1] : 0.f;
            float v0 = acc[mf][nf][0] + b0v, v1 = acc[mf][nf][1] + b1v;
            float v2 = acc[mf][nf][2] + b0v, v3 = acc[mf][nf][3] + b1v;
            float* p0 = &C[(long)row * N + col];
            float* p1 = &C[(long)(row + 8) * N + col];
            if (atomic) {
                atomicAdd(p0, v0); atomicAdd(p0 + 1, v1);
                atomicAdd(p1, v2); atomicAdd(p1 + 1, v3);
            } else {
                p0[0] = v0; p0[1] = v1;
                p1[0] = v2; p1[1] = v3;
            }
        }
}

// -------- GRU gates -> h_new, float4-vectorized (+ zero expsum) ----------
__global__ __launch_bounds__(256) void gru_kernel(const float* __restrict__ hidden,
                                                  float* __restrict__ out) {
    int i4 = blockIdx.x * 256 + threadIdx.x;
    if (i4 < Bb) g_expsum[i4] = 0.f;
    int e = i4 * 4;
    int b = e >> 10, j = e & 1023;
    const float4* gi = reinterpret_cast<const float4*>(&g_gi[b * 3 * Hh + j]);
    const float4* gh = reinterpret_cast<const float4*>(&g_gh[b * 3 * Hh + j]);
    float4 ir = gi[0], iz = gi[Hh / 4], in_ = gi[2 * Hh / 4];
    float4 hr = gh[0], hz = gh[Hh / 4], hn_ = gh[2 * Hh / 4];
    float4 h = *reinterpret_cast<const float4*>(&hidden[e]);

    float4 o;
#pragma unroll
    for (int q = 0; q < 4; q++) {
        float irq = (&ir.x)[q], izq = (&iz.x)[q], inq = (&in_.x)[q];
        float hrq = (&hr.x)[q], hzq = (&hz.x)[q], hnq = (&hn_.x)[q];
        float hq = (&h.x)[q];
        float r = 1.f / (1.f + __expf(-(irq + hrq)));
        float z = 1.f / (1.f + __expf(-(izq + hzq)));
        float n = tanhf(inq + r * hnq);
        (&o.x)[q] = (1.f - z) * n + z * hq;
    }
    *reinterpret_cast<float4*>(&out[(long)Bb * Vv + e]) = o;
    uint2 hb;
    hb.x = pack_bf2(o.x, o.y);
    hb.y = pack_bf2(o.z, o.w);
    *reinterpret_cast<uint2*>(&g_hnbf[e]) = hb;
}

// ======== big GEMM: logits = h_new @ out_W^T + out_b (+ partial expsum) ====
// BM=128, BN=128, BK=32; 256 threads; 8 warps (2M x 4N), warp tile 64x32.
// A (bf16): cp.async 3-stage.  B (fp32->bf16): LDG + cvt + STS, 2-stage.
// grid = (2, 393): x = M-half (adjacent bids share the N-tile -> L2 reuse of W).
#define BIG_NS 32
#define A_STAGE 10240
#define B_STAGE 10240
#define B_OFF   (3 * A_STAGE)
#define BIG_SMEM (3 * A_STAGE + 2 * B_STAGE)

__global__ __launch_bounds__(256, 2) void gemm_big2(
    const __nv_bfloat16* __restrict__ Abf, const float* __restrict__ W,
    const float* __restrict__ ob, float* __restrict__ out) {
    extern __shared__ char dsm[];
    uint32_t dyn = smem_u32(dsm);

    const int tid = threadIdx.x, wid = tid >> 5, lane = tid & 31;
    const int wM = wid & 1, wN = wid >> 1;
    const int g = lane >> 2, t = lane & 3;
    const int m0 = blockIdx.x * 128;
    const long n0 = (long)blockIdx.y * 128;

    const int arow = tid >> 1, aq = (tid & 1) * 2;
    const int brow = tid >> 1, bh = tid & 1;
    const long bn = n0 + brow;
    const bool bok = bn < Vv;
    const __nv_bfloat16* asrc_base = Abf + (long)(m0 + arow) * Hh + aq * 8;
    const float* bsrc_base = W + bn * Hh + bh * 16;

    float acc[4][4][4];
#pragma unroll
    for (int i = 0; i < 4; i++)
#pragma unroll
        for (int j = 0; j < 4; j++)
#pragma unroll
            for (int q = 0; q < 4; q++) acc[i][j][q] = 0.f;

    float4 rb[4];

#define LDG_B(s)                                                              \
    if (bok) {                                                                \
        const float4* p = reinterpret_cast<const float4*>(bsrc_base + (s) * 32); \
        rb[0] = p[0]; rb[1] = p[1]; rb[2] = p[2]; rb[3] = p[3];               \
    } else {                                                                  \
        rb[0] = rb[1] = rb[2] = rb[3] = make_float4(0.f, 0.f, 0.f, 0.f);      \
    }

#define STS_B(buf)                                                            \
    {                                                                         \
        uint32_t bb = dyn + B_OFF + (buf) * B_STAGE + brow * 80 + bh * 32;    \
        uint4 u0, u1;                                                         \
        u0.x = pack_bf2(rb[0].x, rb[0].y); u0.y = pack_bf2(rb[0].z, rb[0].w); \
        u0.z = pack_bf2(rb[1].x, rb[1].y); u0.w = pack_bf2(rb[1].z, rb[1].w); \
        u1.x = pack_bf2(rb[2].x, rb[2].y); u1.y = pack_bf2(rb[2].z, rb[2].w); \
        u1.z = pack_bf2(rb[3].x, rb[3].y); u1.w = pack_bf2(rb[3].z, rb[3].w); \
        sts128(bb, u0); sts128(bb + 16, u1);                                  \
    }

#define CPA_A(s)                                                              \
    {                                                                         \
        uint32_t ab = dyn + ((s) % 3) * A_STAGE + arow * 80 + aq * 16;        \
        const __nv_bfloat16* sp = asrc_base + (s) * 32;                       \
        CP_ASYNC16(ab, sp);                                                   \
        CP_ASYNC16(ab + 16, sp + 8);                                          \
    }

    LDG_B(0); STS_B(0);
    CPA_A(0); CP_COMMIT();
    CPA_A(1); CP_COMMIT();
    LDG_B(1);
    CP_WAIT(1);
    __syncthreads();

    for (int s = 0; s < BIG_NS; s++) {
        if (s + 2 < BIG_NS) { CPA_A(s + 2); CP_COMMIT(); }

        uint32_t ab = dyn + (s % 3) * A_STAGE;
        uint32_t bb = dyn + B_OFF + (s % 2) * B_STAGE;
        int l15 = lane & 15, l16 = (lane >> 4) * 16;
#pragma unroll
        for (int kf = 0; kf < 2; kf++) {
            unsigned a[4][4], b[4][2];
#pragma unroll
            for (int mf = 0; mf < 4; mf++)
                ldm_x4(a[mf], ab + (wM * 64 + mf * 16 + l15) * 80 + kf * 32 + l16);
#pragma unroll
            for (int pr = 0; pr < 2; pr++) {
                unsigned r[4];
                ldm_x4(r, bb + (wN * 32 + pr * 16 + l15) * 80 + kf * 32 + l16);
                b[pr * 2][0] = r[0]; b[pr * 2][1] = r[2];
                b[pr * 2 + 1][0] = r[1]; b[pr * 2 + 1][1] = r[3];
            }
#pragma unroll
            for (int mf = 0; mf < 4; mf++)
#pragma unroll
                for (int nf = 0; nf < 4; nf++)
                    mma_bf16(acc[mf][nf], a[mf][0], a[mf][1], a[mf][2], a[mf][3],
                             b[nf][0], b[nf][1]);
        }

        if (s + 1 < BIG_NS) STS_B((s + 1) & 1);
        if (s + 2 < BIG_NS) { LDG_B(s + 2); CP_WAIT(1); }
        else                { CP_WAIT(0); }
        __syncthreads();
    }
#undef LDG_B
#undef STS_B
#undef CPA_A

#pragma unroll
    for (int mf = 0; mf < 4; mf++) {
        int m = m0 + wM * 64 + mf * 16 + g;
        float s0 = 0.f, s1 = 0.f;
#pragma unroll
        for (int nf = 0; nf < 4; nf++) {
            long col = n0 + wN * 32 + nf * 8 + 2 * t;
            if (col < Vv) {
                float b0 = ob[col];
                float v0 = acc[mf][nf][0] + b0;
                float v2 = acc[mf][nf][2] + b0;
                out[(long)m * Vv + col] = v0;
                out[(long)(m + 8) * Vv + col] = v2;
                s0 += __expf(v0); s1 += __expf(v2);
            }
            if (col + 1 < Vv) {
                float b1 = ob[col + 1];
                float v1 = acc[mf][nf][1] + b1;
                float v3 = acc[mf][nf][3] + b1;
                out[(long)m * Vv + col + 1] = v1;
                out[(long)(m + 8) * Vv + col + 1] = v3;
                s0 += __expf(v1); s1 += __expf(v3);
            }
        }
        s0 += __shfl_xor_sync(0xffffffffu, s0, 1);
        s0 += __shfl_xor_sync(0xffffffffu, s0, 2);
        s1 += __shfl_xor_sync(0xffffffffu, s1, 1);
        s1 += __shfl_xor_sync(0xffffffffu, s1, 2);
        if (t == 0) {
            atomicAdd(&g_expsum[m], s0);
            atomicAdd(&g_expsum[m + 8], s1);
        }
    }
}

// -------- log_softmax subtract: flat float4 pass over the logit block -----
#define E_TOT ((long)Bb * Vv)            // 12,865,792 (divisible by 4)
#define F_TOT (E_TOT / 4)                // float4 count
#define LSE_BLOCKS ((int)((F_TOT + 255) / 256))

__global__ __launch_bounds__(256) void lse_sub(float* __restrict__ out) {
    const long f0 = (long)blockIdx.x * 256;
    const int tid = threadIdx.x;
    __shared__ float slse[2];
    __shared__ int srow0;
    if (tid == 0) {
        int r0 = (int)((f0 * 4) / Vv);
        srow0 = r0;
        slse[0] = logf(g_expsum[r0]);
        long e_last = (f0 + 256) * 4 - 1;
        if (e_last > E_TOT - 1) e_last = E_TOT - 1;
        int r1 = (int)(e_last / Vv);
        slse[1] = (r1 > r0) ? logf(g_expsum[r1]) : slse[0];
    }
    __syncthreads();
    long f = f0 + tid;
    if (f >= F_TOT) return;
    float4 v = reinterpret_cast<float4*>(out)[f];
    long e = f * 4;
    long boundary = (long)(srow0 + 1) * Vv;   // first element of next row
    float l0 = slse[0], l1 = slse[1];
    v.x -= (e + 0 >= boundary) ? l1 : l0;
    v.y -= (e + 1 >= boundary) ? l1 : l0;
    v.z -= (e + 2 >= boundary) ? l1 : l0;
    v.w -= (e + 3 >= boundary) ? l1 : l0;
    reinterpret_cast<float4*>(out)[f] = v;
}

// -------- launch ----------
extern "C" void kernel_launch(void* const* d_in, const int* in_sizes, int n_in,
                              void* d_out, int out_size) {
    const int*   tokens = (const int*)d_in[0];
    const float* hidden = (const float*)d_in[1];
    const float* enc    = (const float*)d_in[2];
    const float* emb    = (const float*)d_in[3];
    const float* attn_W = (const float*)d_in[4];
    const float* attn_b = (const float*)d_in[5];
    const float* comb_W = (const float*)d_in[6];
    const float* comb_b = (const float*)d_in[7];
    const float* W_ih   = (const float*)d_in[8];
    const float* W_hh   = (const float*)d_in[9];
    const float* b_ih   = (const float*)d_in[10];
    const float* b_hh   = (const float*)d_in[11];
    const float* out_W  = (const float*)d_in[12];
    const float* out_b  = (const float*)d_in[13];
    float* out = (float*)d_out;

    float *p_xin, *p_x, *p_gi, *p_gh;
    __nv_bfloat16* p_hn;
    cudaGetSymbolAddress((void**)&p_xin, g_xin);
    cudaGetSymbolAddress((void**)&p_x,   g_x);
    cudaGetSymbolAddress((void**)&p_gi,  g_gi);
    cudaGetSymbolAddress((void**)&p_gh,  g_gh);
    cudaGetSymbolAddress((void**)&p_hn,  g_hnbf);

    static int smem_set = 0;
    if (!smem_set) {
        cudaFuncSetAttribute(gemm_big2, cudaFuncAttributeMaxDynamicSharedMemorySize, BIG_SMEM);
        smem_set = 1;
    }

    attn_kernel<<<Bb, 256>>>(tokens, hidden, enc, emb, attn_W, attn_b, out);

    // launch 1: combine (split-K=4, atomic into zeroed g_x) + gh (independent)
    // z = 0..3 -> combine K-slices; z = 4 -> gh = hidden @ W_hh^T
    dim3 g1(3072 / 64, 256 / 128, 5);
    gemm_front2<<<g1, 256>>>(p_xin, comb_W, comb_b, p_x, 0, 1024, 2048,
                             hidden, W_hh, b_hh, p_gh, 0, 3072, 1024,
                             4);

    // launch 2: gi = relu(g_x) @ W_ih^T
    dim3 g2(3072 / 64, 256 / 128, 1);
    gemm_front2<<<g2, 256>>>(p_x, W_ih, b_ih, p_gi, 1, 3072, 1024,
                             p_x, W_ih, b_ih, p_gi, 1, 3072, 1024,
                             1);

    gru_kernel<<<(Bb * Hh) / 1024, 256>>>(hidden, out);

    dim3 gb(2, (Vv + 127) / 128);
    gemm_big2<<<gb, 256, BIG_SMEM>>>(p_hn, out_W, out_b, out);

    lse_sub<<<LSE_BLOCKS, 256>>>(out);
}

// round 15
// speedup vs baseline: 1.0641x; 1.0641x over previous
#include <cuda_runtime.h>
#include <cuda_bf16.h>
#include <cuda_fp16.h>
#include <math.h>
#include <stdint.h>

#define Vv 50257
#define Hh 1024
#define Ll 10
#define Bb 256

// -------- scratch (no allocations allowed; __device__ globals) ----------
__device__ float g_xin[Bb * 2 * Hh];          // concat(embedded, attn_applied)
__device__ float g_x[Bb * Hh];                // combine accum (pre-relu, atomic)
__device__ float g_gi[Bb * 3 * Hh];
__device__ float g_gh[Bb * 3 * Hh];
__device__ __nv_bfloat16 g_hnbf[Bb * Hh];     // h_new in bf16 for the big GEMM
__device__ float g_expsum[Bb];                // per-row sum(exp(logit))

// -------- helpers ----------
__device__ __forceinline__ unsigned pack_bf2(float a, float b) {
    __nv_bfloat162 t = __floats2bfloat162_rn(a, b);
    return *reinterpret_cast<unsigned*>(&t);
}

__device__ __forceinline__ unsigned pack_h2(float a, float b) {
    __half2 t = __floats2half2_rn(a, b);
    return *reinterpret_cast<unsigned*>(&t);
}

__device__ __forceinline__ void mma_bf16(float* d,
    unsigned a0, unsigned a1, unsigned a2, unsigned a3,
    unsigned b0, unsigned b1) {
    asm volatile(
        "mma.sync.aligned.m16n8k16.row.col.f32.bf16.bf16.f32 "
        "{%0,%1,%2,%3}, {%4,%5,%6,%7}, {%8,%9}, {%0,%1,%2,%3};"
        : "+f"(d[0]), "+f"(d[1]), "+f"(d[2]), "+f"(d[3])
        : "r"(a0), "r"(a1), "r"(a2), "r"(a3), "r"(b0), "r"(b1));
}

__device__ __forceinline__ void mma_f16(float* d,
    unsigned a0, unsigned a1, unsigned a2, unsigned a3,
    unsigned b0, unsigned b1) {
    asm volatile(
        "mma.sync.aligned.m16n8k16.row.col.f32.f16.f16.f32 "
        "{%0,%1,%2,%3}, {%4,%5,%6,%7}, {%8,%9}, {%0,%1,%2,%3};"
        : "+f"(d[0]), "+f"(d[1]), "+f"(d[2]), "+f"(d[3])
        : "r"(a0), "r"(a1), "r"(a2), "r"(a3), "r"(b0), "r"(b1));
}

__device__ __forceinline__ uint32_t smem_u32(const void* p) {
    uint32_t a;
    asm("{ .reg .u64 t; cvta.to.shared.u64 t, %1; cvt.u32.u64 %0, t; }" : "=r"(a) : "l"(p));
    return a;
}

__device__ __forceinline__ void sts128(uint32_t addr, uint4 v) {
    asm volatile("st.shared.v4.b32 [%0], {%1,%2,%3,%4};"
                 :: "r"(addr), "r"(v.x), "r"(v.y), "r"(v.z), "r"(v.w) : "memory");
}

__device__ __forceinline__ void ldm_x4(unsigned* r, uint32_t addr) {
    asm volatile("ldmatrix.sync.aligned.m8n8.x4.shared.b16 {%0,%1,%2,%3}, [%4];"
                 : "=r"(r[0]), "=r"(r[1]), "=r"(r[2]), "=r"(r[3]) : "r"(addr));
}

#define CP_ASYNC16(dst, src) \
    asm volatile("cp.async.cg.shared.global [%0], [%1], 16;" :: "r"(dst), "l"(src))
#define CP_COMMIT() asm volatile("cp.async.commit_group;" ::: "memory")
#define CP_WAIT(n)  asm volatile("cp.async.wait_group %0;" :: "n"(n) : "memory")

// -------- K1: embedding gather + attention + zero combine accumulator -----
// float4-vectorized main loops (latency-bound kernel; 4x bytes in flight).
__global__ void attn_kernel(const int* __restrict__ tokens,
                            const float* __restrict__ hidden,
                            const float* __restrict__ enc,
                            const float* __restrict__ emb,
                            const float* __restrict__ attn_W,
                            const float* __restrict__ attn_b,
                            float* __restrict__ out) {
    int b = blockIdx.x, tid = threadIdx.x;
    int tok = tokens[b];
    // zero the split-K accumulator for the combine GEMM (1024 floats = 256 f4)
    reinterpret_cast<float4*>(g_x + b * Hh)[tid] = make_float4(0.f, 0.f, 0.f, 0.f);

    const float4* emb4  = reinterpret_cast<const float4*>(emb);
    const float4* hid4  = reinterpret_cast<const float4*>(hidden);
    const float4* aw4   = reinterpret_cast<const float4*>(attn_W);
    const float4* enc4  = reinterpret_cast<const float4*>(enc);
    float4* xin4 = reinterpret_cast<float4*>(g_xin);

    float part[Ll];
#pragma unroll
    for (int l = 0; l < Ll; l++) part[l] = 0.f;

    // 2048 elements = 512 float4; 256 threads -> 2 iterations
#pragma unroll
    for (int it = 0; it < 2; it++) {
        int k4 = tid + it * 256;
        float4 v;
        if (k4 < 256) { v = emb4[(long)tok * 256 + k4]; xin4[b * 512 + k4] = v; }
        else            v = hid4[b * 256 + (k4 - 256)];
#pragma unroll
        for (int l = 0; l < Ll; l++) {
            float4 wv = aw4[l * 512 + k4];
            part[l] += v.x * wv.x + v.y * wv.y + v.z * wv.z + v.w * wv.w;
        }
    }
#pragma unroll
    for (int l = 0; l < Ll; l++)
#pragma unroll
        for (int o = 16; o; o >>= 1) part[l] += __shfl_xor_sync(0xffffffffu, part[l], o);

    __shared__ float ws[8][Ll];
    __shared__ float wsm[Ll];
    int wid = tid >> 5, lane = tid & 31;
    if (lane == 0)
        for (int l = 0; l < Ll; l++) ws[wid][l] = part[l];
    __syncthreads();
    if (tid == 0) {
        float lg[Ll]; float mx = -1e30f;
        for (int l = 0; l < Ll; l++) {
            float s = attn_b[l];
            for (int w = 0; w < 8; w++) s += ws[w][l];
            lg[l] = s; mx = fmaxf(mx, s);
        }
        float sum = 0.f;
        for (int l = 0; l < Ll; l++) { lg[l] = expf(lg[l] - mx); sum += lg[l]; }
        float inv = 1.f / sum;
        for (int l = 0; l < Ll; l++) wsm[l] = lg[l] * inv;
    }
    __syncthreads();
    if (tid < Ll) out[(long)Bb * Vv + Bb * Hh + b * Ll + tid] = wsm[tid];

    float w[Ll];
#pragma unroll
    for (int l = 0; l < Ll; l++) w[l] = wsm[l];
    // attn_applied: 1024 floats = 256 float4, one per thread
    float4 s = make_float4(0.f, 0.f, 0.f, 0.f);
#pragma unroll
    for (int l = 0; l < Ll; l++) {
        float4 e = enc4[l * 256 + tid];
        s.x += w[l] * e.x; s.y += w[l] * e.y;
        s.z += w[l] * e.z; s.w += w[l] * e.w;
    }
    xin4[b * 512 + 256 + tid] = s;
}

// ======== front GEMM: C = A @ W^T (+bias), fp16 A x fp16 W ================
#define F_ASTG 10240
#define F_WSTG 5120
#define F_STG  (F_ASTG + F_WSTG)

__global__ __launch_bounds__(256, 2) void gemm_front2(
    const float* __restrict__ A0, const float* __restrict__ W0,
    const float* __restrict__ b0, float* __restrict__ C0, int relu0,
    const float* __restrict__ A1, const float* __restrict__ W1,
    const float* __restrict__ b1, float* __restrict__ C1, int relu1,
    int N, int K, int ksplit, int atomic) {
    __shared__ __align__(16) char smf[2 * F_STG];
    uint32_t base = smem_u32(smf);

    int prob, kz;
    if (ksplit > 1) { prob = 0; kz = blockIdx.z; }
    else            { prob = blockIdx.z; kz = 0; }
    const float* A    = prob ? A1 : A0;
    const float* W    = prob ? W1 : W0;
    const float* bias = prob ? b1 : b0;
    float*       C    = prob ? C1 : C0;
    const int relu_a  = prob ? relu1 : relu0;

    const int Kloc = K / ksplit;
    const int kbase = kz * Kloc;
    const int NS = Kloc >> 5;

    const int tid = threadIdx.x, wid = tid >> 5, lane = tid & 31;
    const int wM = wid & 1, wN = wid >> 1;
    const int g = lane >> 2, t = lane & 3;
    const int m0 = blockIdx.y * 128;
    const int n0 = blockIdx.x * 64;

    const int arow = tid >> 1, ahf = tid & 1;
    const int wrow = tid >> 2, wq = tid & 3;
    const float* asrc = A + (long)(m0 + arow) * K + kbase + ahf * 16;
    const float* wsrc = W + (long)(n0 + wrow) * K + kbase + wq * 8;

    float acc[4][2][4];
#pragma unroll
    for (int i = 0; i < 4; i++)
#pragma unroll
        for (int j = 0; j < 2; j++)
#pragma unroll
            for (int q = 0; q < 4; q++) acc[i][j][q] = 0.f;

    float ra[16], rw[8];

#define LDG_F(s)                                                          \
    {                                                                     \
        const float4* pa = reinterpret_cast<const float4*>(asrc + (s) * 32); \
        reinterpret_cast<float4*>(ra)[0] = pa[0];                         \
        reinterpret_cast<float4*>(ra)[1] = pa[1];                         \
        reinterpret_cast<float4*>(ra)[2] = pa[2];                         \
        reinterpret_cast<float4*>(ra)[3] = pa[3];                         \
        const float4* pw = reinterpret_cast<const float4*>(wsrc + (s) * 32); \
        reinterpret_cast<float4*>(rw)[0] = pw[0];                         \
        reinterpret_cast<float4*>(rw)[1] = pw[1];                         \
    }

#define RL(v) (relu_a ? fmaxf(v, 0.f) : (v))

#define STS_F(buf)                                                        \
    {                                                                     \
        uint32_t ab = base + (buf) * F_STG + arow * 80 + ahf * 32;        \
        uint4 u0, u1;                                                     \
        u0.x = pack_h2(RL(ra[0]),  RL(ra[1]));                            \
        u0.y = pack_h2(RL(ra[2]),  RL(ra[3]));                            \
        u0.z = pack_h2(RL(ra[4]),  RL(ra[5]));                            \
        u0.w = pack_h2(RL(ra[6]),  RL(ra[7]));                            \
        u1.x = pack_h2(RL(ra[8]),  RL(ra[9]));                            \
        u1.y = pack_h2(RL(ra[10]), RL(ra[11]));                           \
        u1.z = pack_h2(RL(ra[12]), RL(ra[13]));                           \
        u1.w = pack_h2(RL(ra[14]), RL(ra[15]));                           \
        sts128(ab, u0); sts128(ab + 16, u1);                              \
        uint32_t whb = base + (buf) * F_STG + F_ASTG + wrow * 80 + wq * 16; \
        uint4 h;                                                          \
        h.x = pack_h2(rw[0], rw[1]);                                      \
        h.y = pack_h2(rw[2], rw[3]);                                      \
        h.z = pack_h2(rw[4], rw[5]);                                      \
        h.w = pack_h2(rw[6], rw[7]);                                      \
        sts128(whb, h);                                                   \
    }

    LDG_F(0); STS_F(0);
    if (NS > 1) LDG_F(1);
    __syncthreads();

    const int l15 = lane & 15, l16o = (lane >> 4) * 16;
    for (int s = 0; s < NS; s++) {
        int buf = s & 1;
        uint32_t ab = base + buf * F_STG;
        uint32_t whb = ab + F_ASTG;
#pragma unroll
        for (int kf = 0; kf < 2; kf++) {
            unsigned a[4][4], bh[2][2], r[4];
#pragma unroll
            for (int mf = 0; mf < 4; mf++)
                ldm_x4(a[mf], ab + (wM * 64 + mf * 16 + l15) * 80 + kf * 32 + l16o);
            ldm_x4(r, whb + (wN * 16 + l15) * 80 + kf * 32 + l16o);
            bh[0][0] = r[0]; bh[0][1] = r[2]; bh[1][0] = r[1]; bh[1][1] = r[3];
#pragma unroll
            for (int mf = 0; mf < 4; mf++)
#pragma unroll
                for (int nf = 0; nf < 2; nf++)
                    mma_f16(acc[mf][nf], a[mf][0], a[mf][1], a[mf][2], a[mf][3],
                            bh[nf][0], bh[nf][1]);
        }
        if (s + 1 < NS) STS_F((s + 1) & 1);
        if (s + 2 < NS) LDG_F(s + 2);
        __syncthreads();
    }
#undef LDG_F
#undef STS_F
#undef RL

#pragma unroll
    for (int mf = 0; mf < 4; mf++)
#pragma unroll
        for (int nf = 0; nf < 2; nf++) {
            int row = m0 + wM * 64 + mf * 16 + g;
            int col = n0 + wN * 16 + nf * 8 + t * 2;
            float b0v = (kz == 0) ? bias[col] : 0.f;
            float b1v = (kz == 0) ? bias[col + 1] : 0.f;
            float v0 = acc[mf][nf][0] + b0v, v1 = acc[mf][nf][1] + b1v;
            float v2 = acc[mf][nf][2] + b0v, v3 = acc[mf][nf][3] + b1v;
            float* p0 = &C[(long)row * N + col];
            float* p1 = &C[(long)(row + 8) * N + col];
            if (atomic) {
                atomicAdd(p0, v0); atomicAdd(p0 + 1, v1);
                atomicAdd(p1, v2); atomicAdd(p1 + 1, v3);
            } else {
                p0[0] = v0; p0[1] = v1;
                p1[0] = v2; p1[1] = v3;
            }
        }
}

// -------- GRU gates -> h_new, float4-vectorized (+ zero expsum) ----------
__global__ __launch_bounds__(256) void gru_kernel(const float* __restrict__ hidden,
                                                  float* __restrict__ out) {
    int i4 = blockIdx.x * 256 + threadIdx.x;
    if (i4 < Bb) g_expsum[i4] = 0.f;
    int e = i4 * 4;
    int b = e >> 10, j = e & 1023;
    const float4* gi = reinterpret_cast<const float4*>(&g_gi[b * 3 * Hh + j]);
    const float4* gh = reinterpret_cast<const float4*>(&g_gh[b * 3 * Hh + j]);
    float4 ir = gi[0], iz = gi[Hh / 4], in_ = gi[2 * Hh / 4];
    float4 hr = gh[0], hz = gh[Hh / 4], hn_ = gh[2 * Hh / 4];
    float4 h = *reinterpret_cast<const float4*>(&hidden[e]);

    float4 o;
#pragma unroll
    for (int q = 0; q < 4; q++) {
        float irq = (&ir.x)[q], izq = (&iz.x)[q], inq = (&in_.x)[q];
        float hrq = (&hr.x)[q], hzq = (&hz.x)[q], hnq = (&hn_.x)[q];
        float hq = (&h.x)[q];
        float r = 1.f / (1.f + __expf(-(irq + hrq)));
        float z = 1.f / (1.f + __expf(-(izq + hzq)));
        float n = tanhf(inq + r * hnq);
        (&o.x)[q] = (1.f - z) * n + z * hq;
    }
    *reinterpret_cast<float4*>(&out[(long)Bb * Vv + e]) = o;
    uint2 hb;
    hb.x = pack_bf2(o.x, o.y);
    hb.y = pack_bf2(o.z, o.w);
    *reinterpret_cast<uint2*>(&g_hnbf[e]) = hb;
}

// ======== big GEMM: logits = h_new @ out_W^T + out_b (+ partial expsum) ====
// BM=128, BN=128, BK=32; 256 threads; 8 warps (2M x 4N), warp tile 64x32.
// A (bf16): cp.async 3-stage.  B (fp32->bf16): LDG + cvt + STS, 2-stage.
// grid = (2, 393): x = M-half (adjacent bids share the N-tile -> L2 reuse of W).
#define BIG_NS 32
#define A_STAGE 10240
#define B_STAGE 10240
#define B_OFF   (3 * A_STAGE)
#define BIG_SMEM (3 * A_STAGE + 2 * B_STAGE)

__global__ __launch_bounds__(256, 2) void gemm_big2(
    const __nv_bfloat16* __restrict__ Abf, const float* __restrict__ W,
    const float* __restrict__ ob, float* __restrict__ out) {
    extern __shared__ char dsm[];
    uint32_t dyn = smem_u32(dsm);

    const int tid = threadIdx.x, wid = tid >> 5, lane = tid & 31;
    const int wM = wid & 1, wN = wid >> 1;
    const int g = lane >> 2, t = lane & 3;
    const int m0 = blockIdx.x * 128;
    const long n0 = (long)blockIdx.y * 128;

    const int arow = tid >> 1, aq = (tid & 1) * 2;
    const int brow = tid >> 1, bh = tid & 1;
    const long bn = n0 + brow;
    const bool bok = bn < Vv;
    const __nv_bfloat16* asrc_base = Abf + (long)(m0 + arow) * Hh + aq * 8;
    const float* bsrc_base = W + bn * Hh + bh * 16;

    float acc[4][4][4];
#pragma unroll
    for (int i = 0; i < 4; i++)
#pragma unroll
        for (int j = 0; j < 4; j++)
#pragma unroll
            for (int q = 0; q < 4; q++) acc[i][j][q] = 0.f;

    float4 rb[4];

#define LDG_B(s)                                                              \
    if (bok) {                                                                \
        const float4* p = reinterpret_cast<const float4*>(bsrc_base + (s) * 32); \
        rb[0] = p[0]; rb[1] = p[1]; rb[2] = p[2]; rb[3] = p[3];               \
    } else {                                                                  \
        rb[0] = rb[1] = rb[2] = rb[3] = make_float4(0.f, 0.f, 0.f, 0.f);      \
    }

#define STS_B(buf)                                                            \
    {                                                                         \
        uint32_t bb = dyn + B_OFF + (buf) * B_STAGE + brow * 80 + bh * 32;    \
        uint4 u0, u1;                                                         \
        u0.x = pack_bf2(rb[0].x, rb[0].y); u0.y = pack_bf2(rb[0].z, rb[0].w); \
        u0.z = pack_bf2(rb[1].x, rb[1].y); u0.w = pack_bf2(rb[1].z, rb[1].w); \
        u1.x = pack_bf2(rb[2].x, rb[2].y); u1.y = pack_bf2(rb[2].z, rb[2].w); \
        u1.z = pack_bf2(rb[3].x, rb[3].y); u1.w = pack_bf2(rb[3].z, rb[3].w); \
        sts128(bb, u0); sts128(bb + 16, u1);                                  \
    }

#define CPA_A(s)                                                              \
    {                                                                         \
        uint32_t ab = dyn + ((s) % 3) * A_STAGE + arow * 80 + aq * 16;        \
        const __nv_bfloat16* sp = asrc_base + (s) * 32;                       \
        CP_ASYNC16(ab, sp);                                                   \
        CP_ASYNC16(ab + 16, sp + 8);                                          \
    }

    LDG_B(0); STS_B(0);
    CPA_A(0); CP_COMMIT();
    CPA_A(1); CP_COMMIT();
    LDG_B(1);
    CP_WAIT(1);
    __syncthreads();

    for (int s = 0; s < BIG_NS; s++) {
        if (s + 2 < BIG_NS) { CPA_A(s + 2); CP_COMMIT(); }

        uint32_t ab = dyn + (s % 3) * A_STAGE;
        uint32_t bb = dyn + B_OFF + (s % 2) * B_STAGE;
        int l15 = lane & 15, l16 = (lane >> 4) * 16;
#pragma unroll
        for (int kf = 0; kf < 2; kf++) {
            unsigned a[4][4], b[4][2];
#pragma unroll
            for (int mf = 0; mf < 4; mf++)
                ldm_x4(a[mf], ab + (wM * 64 + mf * 16 + l15) * 80 + kf * 32 + l16);
#pragma unroll
            for (int pr = 0; pr < 2; pr++) {
                unsigned r[4];
                ldm_x4(r, bb + (wN * 32 + pr * 16 + l15) * 80 + kf * 32 + l16);
                b[pr * 2][0] = r[0]; b[pr * 2][1] = r[2];
                b[pr * 2 + 1][0] = r[1]; b[pr * 2 + 1][1] = r[3];
            }
#pragma unroll
            for (int mf = 0; mf < 4; mf++)
#pragma unroll
                for (int nf = 0; nf < 4; nf++)
                    mma_bf16(acc[mf][nf], a[mf][0], a[mf][1], a[mf][2], a[mf][3],
                             b[nf][0], b[nf][1]);
        }

        if (s + 1 < BIG_NS) STS_B((s + 1) & 1);
        if (s + 2 < BIG_NS) { LDG_B(s + 2); CP_WAIT(1); }
        else                { CP_WAIT(0); }
        __syncthreads();
    }
#undef LDG_B
#undef STS_B
#undef CPA_A

#pragma unroll
    for (int mf = 0; mf < 4; mf++) {
        int m = m0 + wM * 64 + mf * 16 + g;
        float s0 = 0.f, s1 = 0.f;
#pragma unroll
        for (int nf = 0; nf < 4; nf++) {
            long col = n0 + wN * 32 + nf * 8 + 2 * t;
            if (col < Vv) {
                float b0 = ob[col];
                float v0 = acc[mf][nf][0] + b0;
                float v2 = acc[mf][nf][2] + b0;
                out[(long)m * Vv + col] = v0;
                out[(long)(m + 8) * Vv + col] = v2;
                s0 += __expf(v0); s1 += __expf(v2);
            }
            if (col + 1 < Vv) {
                float b1 = ob[col + 1];
                float v1 = acc[mf][nf][1] + b1;
                float v3 = acc[mf][nf][3] + b1;
                out[(long)m * Vv + col + 1] = v1;
                out[(long)(m + 8) * Vv + col + 1] = v3;
                s0 += __expf(v1); s1 += __expf(v3);
            }
        }
        s0 += __shfl_xor_sync(0xffffffffu, s0, 1);
        s0 += __shfl_xor_sync(0xffffffffu, s0, 2);
        s1 += __shfl_xor_sync(0xffffffffu, s1, 1);
        s1 += __shfl_xor_sync(0xffffffffu, s1, 2);
        if (t == 0) {
            atomicAdd(&g_expsum[m], s0);
            atomicAdd(&g_expsum[m + 8], s1);
        }
    }
}

// -------- log_softmax subtract: flat float4 pass over the logit block -----
#define E_TOT ((long)Bb * Vv)            // 12,865,792 (divisible by 4)
#define F_TOT (E_TOT / 4)                // float4 count
#define LSE_BLOCKS ((int)((F_TOT + 255) / 256))

__global__ __launch_bounds__(256) void lse_sub(float* __restrict__ out) {
    const long f0 = (long)blockIdx.x * 256;
    const int tid = threadIdx.x;
    __shared__ float slse[2];
    __shared__ int srow0;
    if (tid == 0) {
        int r0 = (int)((f0 * 4) / Vv);
        srow0 = r0;
        slse[0] = logf(g_expsum[r0]);
        long e_last = (f0 + 256) * 4 - 1;
        if (e_last > E_TOT - 1) e_last = E_TOT - 1;
        int r1 = (int)(e_last / Vv);
        slse[1] = (r1 > r0) ? logf(g_expsum[r1]) : slse[0];
    }
    __syncthreads();
    long f = f0 + tid;
    if (f >= F_TOT) return;
    float4 v = reinterpret_cast<float4*>(out)[f];
    long e = f * 4;
    long boundary = (long)(srow0 + 1) * Vv;   // first element of next row
    float l0 = slse[0], l1 = slse[1];
    v.x -= (e + 0 >= boundary) ? l1 : l0;
    v.y -= (e + 1 >= boundary) ? l1 : l0;
    v.z -= (e + 2 >= boundary) ? l1 : l0;
    v.w -= (e + 3 >= boundary) ? l1 : l0;
    reinterpret_cast<float4*>(out)[f] = v;
}

// -------- launch ----------
extern "C" void kernel_launch(void* const* d_in, const int* in_sizes, int n_in,
                              void* d_out, int out_size) {
    const int*   tokens = (const int*)d_in[0];
    const float* hidden = (const float*)d_in[1];
    const float* enc    = (const float*)d_in[2];
    const float* emb    = (const float*)d_in[3];
    const float* attn_W = (const float*)d_in[4];
    const float* attn_b = (const float*)d_in[5];
    const float* comb_W = (const float*)d_in[6];
    const float* comb_b = (const float*)d_in[7];
    const float* W_ih   = (const float*)d_in[8];
    const float* W_hh   = (const float*)d_in[9];
    const float* b_ih   = (const float*)d_in[10];
    const float* b_hh   = (const float*)d_in[11];
    const float* out_W  = (const float*)d_in[12];
    const float* out_b  = (const float*)d_in[13];
    float* out = (float*)d_out;

    float *p_xin, *p_x, *p_gi, *p_gh;
    __nv_bfloat16* p_hn;
    cudaGetSymbolAddress((void**)&p_xin, g_xin);
    cudaGetSymbolAddress((void**)&p_x,   g_x);
    cudaGetSymbolAddress((void**)&p_gi,  g_gi);
    cudaGetSymbolAddress((void**)&p_gh,  g_gh);
    cudaGetSymbolAddress((void**)&p_hn,  g_hnbf);

    static int smem_set = 0;
    if (!smem_set) {
        cudaFuncSetAttribute(gemm_big2, cudaFuncAttributeMaxDynamicSharedMemorySize, BIG_SMEM);
        smem_set = 1;
    }

    attn_kernel<<<Bb, 256>>>(tokens, hidden, enc, emb, attn_W, attn_b, out);

    // combine (split-K=4, atomic accumulate into zeroed g_x; relu deferred)
    dim3 gc(1024 / 64, 256 / 128, 4);
    gemm_front2<<<gc, 256>>>(p_xin, comb_W, comb_b, p_x, 0,
                             p_xin, comb_W, comb_b, p_x, 0,
                             1024, 2048, 4, 1);

    // gi = relu(g_x) @ W_ih^T ; gh = hidden @ W_hh^T  (merged via blockIdx.z)
    dim3 gg(3072 / 64, 256 / 128, 2);
    gemm_front2<<<gg, 256>>>(p_x, W_ih, b_ih, p_gi, 1,
                             hidden, W_hh, b_hh, p_gh, 0,
                             3072, 1024, 1, 0);

    gru_kernel<<<(Bb * Hh) / 1024, 256>>>(hidden, out);

    dim3 gb(2, (Vv + 127) / 128);
    gemm_big2<<<gb, 256, BIG_SMEM>>>(p_hn, out_W, out_b, out);

    lse_sub<<<LSE_BLOCKS, 256>>>(out);
}

// round 16
// speedup vs baseline: 1.0951x; 1.0291x over previous
#include <cuda_runtime.h>
#include <cuda_bf16.h>
#include <cuda_fp16.h>
#include <math.h>
#include <stdint.h>

#define Vv 50257
#define Hh 1024
#define Ll 10
#define Bb 256

// -------- scratch (no allocations allowed; __device__ globals) ----------
__device__ float g_xin[Bb * 2 * Hh];          // concat(embedded, attn_applied)
__device__ float g_x[Bb * Hh];                // combine accum (pre-relu, atomic)
__device__ float g_gi[Bb * 3 * Hh];           // gi K-slice 0
__device__ float g_gi2[Bb * 3 * Hh];          // gi K-slice 1
__device__ float g_gh[Bb * 3 * Hh];           // gh K-slice 0
__device__ float g_gh2[Bb * 3 * Hh];          // gh K-slice 1
__device__ __nv_bfloat16 g_hnbf[Bb * Hh];     // h_new in bf16 for the big GEMM
__device__ float g_expsum[Bb];                // per-row sum(exp(logit))

// -------- helpers ----------
__device__ __forceinline__ unsigned pack_bf2(float a, float b) {
    __nv_bfloat162 t = __floats2bfloat162_rn(a, b);
    return *reinterpret_cast<unsigned*>(&t);
}

__device__ __forceinline__ unsigned pack_h2(float a, float b) {
    __half2 t = __floats2half2_rn(a, b);
    return *reinterpret_cast<unsigned*>(&t);
}

__device__ __forceinline__ void mma_bf16(float* d,
    unsigned a0, unsigned a1, unsigned a2, unsigned a3,
    unsigned b0, unsigned b1) {
    asm volatile(
        "mma.sync.aligned.m16n8k16.row.col.f32.bf16.bf16.f32 "
        "{%0,%1,%2,%3}, {%4,%5,%6,%7}, {%8,%9}, {%0,%1,%2,%3};"
        : "+f"(d[0]), "+f"(d[1]), "+f"(d[2]), "+f"(d[3])
        : "r"(a0), "r"(a1), "r"(a2), "r"(a3), "r"(b0), "r"(b1));
}

__device__ __forceinline__ void mma_f16(float* d,
    unsigned a0, unsigned a1, unsigned a2, unsigned a3,
    unsigned b0, unsigned b1) {
    asm volatile(
        "mma.sync.aligned.m16n8k16.row.col.f32.f16.f16.f32 "
        "{%0,%1,%2,%3}, {%4,%5,%6,%7}, {%8,%9}, {%0,%1,%2,%3};"
        : "+f"(d[0]), "+f"(d[1]), "+f"(d[2]), "+f"(d[3])
        : "r"(a0), "r"(a1), "r"(a2), "r"(a3), "r"(b0), "r"(b1));
}

__device__ __forceinline__ uint32_t smem_u32(const void* p) {
    uint32_t a;
    asm("{ .reg .u64 t; cvta.to.shared.u64 t, %1; cvt.u32.u64 %0, t; }" : "=r"(a) : "l"(p));
    return a;
}

__device__ __forceinline__ void sts128(uint32_t addr, uint4 v) {
    asm volatile("st.shared.v4.b32 [%0], {%1,%2,%3,%4};"
                 :: "r"(addr), "r"(v.x), "r"(v.y), "r"(v.z), "r"(v.w) : "memory");
}

__device__ __forceinline__ void ldm_x4(unsigned* r, uint32_t addr) {
    asm volatile("ldmatrix.sync.aligned.m8n8.x4.shared.b16 {%0,%1,%2,%3}, [%4];"
                 : "=r"(r[0]), "=r"(r[1]), "=r"(r[2]), "=r"(r[3]) : "r"(addr));
}

#define CP_ASYNC16(dst, src) \
    asm volatile("cp.async.cg.shared.global [%0], [%1], 16;" :: "r"(dst), "l"(src))
#define CP_COMMIT() asm volatile("cp.async.commit_group;" ::: "memory")
#define CP_WAIT(n)  asm volatile("cp.async.wait_group %0;" :: "n"(n) : "memory")

// -------- K1: embedding gather + attention + zero combine accumulator -----
__global__ void attn_kernel(const int* __restrict__ tokens,
                            const float* __restrict__ hidden,
                            const float* __restrict__ enc,
                            const float* __restrict__ emb,
                            const float* __restrict__ attn_W,
                            const float* __restrict__ attn_b,
                            float* __restrict__ out) {
    int b = blockIdx.x, tid = threadIdx.x;
    int tok = tokens[b];
    reinterpret_cast<float4*>(g_x + b * Hh)[tid] = make_float4(0.f, 0.f, 0.f, 0.f);

    const float4* emb4  = reinterpret_cast<const float4*>(emb);
    const float4* hid4  = reinterpret_cast<const float4*>(hidden);
    const float4* aw4   = reinterpret_cast<const float4*>(attn_W);
    const float4* enc4  = reinterpret_cast<const float4*>(enc);
    float4* xin4 = reinterpret_cast<float4*>(g_xin);

    float part[Ll];
#pragma unroll
    for (int l = 0; l < Ll; l++) part[l] = 0.f;

#pragma unroll
    for (int it = 0; it < 2; it++) {
        int k4 = tid + it * 256;
        float4 v;
        if (k4 < 256) { v = emb4[(long)tok * 256 + k4]; xin4[b * 512 + k4] = v; }
        else            v = hid4[b * 256 + (k4 - 256)];
#pragma unroll
        for (int l = 0; l < Ll; l++) {
            float4 wv = aw4[l * 512 + k4];
            part[l] += v.x * wv.x + v.y * wv.y + v.z * wv.z + v.w * wv.w;
        }
    }
#pragma unroll
    for (int l = 0; l < Ll; l++)
#pragma unroll
        for (int o = 16; o; o >>= 1) part[l] += __shfl_xor_sync(0xffffffffu, part[l], o);

    __shared__ float ws[8][Ll];
    __shared__ float wsm[Ll];
    int wid = tid >> 5, lane = tid & 31;
    if (lane == 0)
        for (int l = 0; l < Ll; l++) ws[wid][l] = part[l];
    __syncthreads();
    if (tid == 0) {
        float lg[Ll]; float mx = -1e30f;
        for (int l = 0; l < Ll; l++) {
            float s = attn_b[l];
            for (int w = 0; w < 8; w++) s += ws[w][l];
            lg[l] = s; mx = fmaxf(mx, s);
        }
        float sum = 0.f;
        for (int l = 0; l < Ll; l++) { lg[l] = expf(lg[l] - mx); sum += lg[l]; }
        float inv = 1.f / sum;
        for (int l = 0; l < Ll; l++) wsm[l] = lg[l] * inv;
    }
    __syncthreads();
    if (tid < Ll) out[(long)Bb * Vv + Bb * Hh + b * Ll + tid] = wsm[tid];

    float w[Ll];
#pragma unroll
    for (int l = 0; l < Ll; l++) w[l] = wsm[l];
    float4 s = make_float4(0.f, 0.f, 0.f, 0.f);
#pragma unroll
    for (int l = 0; l < Ll; l++) {
        float4 e = enc4[l * 256 + tid];
        s.x += w[l] * e.x; s.y += w[l] * e.y;
        s.z += w[l] * e.z; s.w += w[l] * e.w;
    }
    xin4[b * 512 + 256 + tid] = s;
}

// ======== front GEMM: C = A @ W^T (+bias), fp16 A x fp16 W ================
// mode 0 (combine): blockIdx.z = K-slice (8 slices), atomicAdd into C0.
// mode 1 (gates):   z in {0,1} -> problem 0 K-slice z (C0 / C0b);
//                   z in {2,3} -> problem 1 K-slice z-2 (C1 / C1b).
//                   Slices write their own buffer, no atomics; bias on slice 0.
#define F_ASTG 10240
#define F_WSTG 5120
#define F_STG  (F_ASTG + F_WSTG)

__global__ __launch_bounds__(256, 2) void gemm_front2(
    const float* __restrict__ A0, const float* __restrict__ W0,
    const float* __restrict__ b0, float* __restrict__ C0,
    float* __restrict__ C0b, int relu0,
    const float* __restrict__ A1, const float* __restrict__ W1,
    const float* __restrict__ b1, float* __restrict__ C1,
    float* __restrict__ C1b, int relu1,
    int N, int K, int mode) {
    __shared__ __align__(16) char smf[2 * F_STG];
    uint32_t base = smem_u32(smf);

    int prob, kz, Kloc, atomic;
    if (mode == 0) { prob = 0; kz = blockIdx.z; Kloc = K >> 3; atomic = 1; }
    else           { prob = ((int)blockIdx.z >= 2); kz = blockIdx.z & 1; Kloc = K >> 1; atomic = 0; }

    const float* A    = prob ? A1 : A0;
    const float* W    = prob ? W1 : W0;
    const float* bias = prob ? b1 : b0;
    float* C;
    if (atomic) C = C0;
    else        C = prob ? (kz ? C1b : C1) : (kz ? C0b : C0);
    const int relu_a  = prob ? relu1 : relu0;

    const int kbase = kz * Kloc;
    const int NS = Kloc >> 5;

    const int tid = threadIdx.x, wid = tid >> 5, lane = tid & 31;
    const int wM = wid & 1, wN = wid >> 1;
    const int g = lane >> 2, t = lane & 3;
    const int m0 = blockIdx.y * 128;
    const int n0 = blockIdx.x * 64;

    const int arow = tid >> 1, ahf = tid & 1;
    const int wrow = tid >> 2, wq = tid & 3;
    const float* asrc = A + (long)(m0 + arow) * K + kbase + ahf * 16;
    const float* wsrc = W + (long)(n0 + wrow) * K + kbase + wq * 8;

    float acc[4][2][4];
#pragma unroll
    for (int i = 0; i < 4; i++)
#pragma unroll
        for (int j = 0; j < 2; j++)
#pragma unroll
            for (int q = 0; q < 4; q++) acc[i][j][q] = 0.f;

    float ra[16], rw[8];

#define LDG_F(s)                                                          \
    {                                                                     \
        const float4* pa = reinterpret_cast<const float4*>(asrc + (s) * 32); \
        reinterpret_cast<float4*>(ra)[0] = pa[0];                         \
        reinterpret_cast<float4*>(ra)[1] = pa[1];                         \
        reinterpret_cast<float4*>(ra)[2] = pa[2];                         \
        reinterpret_cast<float4*>(ra)[3] = pa[3];                         \
        const float4* pw = reinterpret_cast<const float4*>(wsrc + (s) * 32); \
        reinterpret_cast<float4*>(rw)[0] = pw[0];                         \
        reinterpret_cast<float4*>(rw)[1] = pw[1];                         \
    }

#define RL(v) (relu_a ? fmaxf(v, 0.f) : (v))

#define STS_F(buf)                                                        \
    {                                                                     \
        uint32_t ab = base + (buf) * F_STG + arow * 80 + ahf * 32;        \
        uint4 u0, u1;                                                     \
        u0.x = pack_h2(RL(ra[0]),  RL(ra[1]));                            \
        u0.y = pack_h2(RL(ra[2]),  RL(ra[3]));                            \
        u0.z = pack_h2(RL(ra[4]),  RL(ra[5]));                            \
        u0.w = pack_h2(RL(ra[6]),  RL(ra[7]));                            \
        u1.x = pack_h2(RL(ra[8]),  RL(ra[9]));                            \
        u1.y = pack_h2(RL(ra[10]), RL(ra[11]));                           \
        u1.z = pack_h2(RL(ra[12]), RL(ra[13]));                           \
        u1.w = pack_h2(RL(ra[14]), RL(ra[15]));                           \
        sts128(ab, u0); sts128(ab + 16, u1);                              \
        uint32_t whb = base + (buf) * F_STG + F_ASTG + wrow * 80 + wq * 16; \
        uint4 h;                                                          \
        h.x = pack_h2(rw[0], rw[1]);                                      \
        h.y = pack_h2(rw[2], rw[3]);                                      \
        h.z = pack_h2(rw[4], rw[5]);                                      \
        h.w = pack_h2(rw[6], rw[7]);                                      \
        sts128(whb, h);                                                   \
    }

    LDG_F(0); STS_F(0);
    if (NS > 1) LDG_F(1);
    __syncthreads();

    const int l15 = lane & 15, l16o = (lane >> 4) * 16;
    for (int s = 0; s < NS; s++) {
        int buf = s & 1;
        uint32_t ab = base + buf * F_STG;
        uint32_t whb = ab + F_ASTG;
#pragma unroll
        for (int kf = 0; kf < 2; kf++) {
            unsigned a[4][4], bh[2][2], r[4];
#pragma unroll
            for (int mf = 0; mf < 4; mf++)
                ldm_x4(a[mf], ab + (wM * 64 + mf * 16 + l15) * 80 + kf * 32 + l16o);
            ldm_x4(r, whb + (wN * 16 + l15) * 80 + kf * 32 + l16o);
            bh[0][0] = r[0]; bh[0][1] = r[2]; bh[1][0] = r[1]; bh[1][1] = r[3];
#pragma unroll
            for (int mf = 0; mf < 4; mf++)
#pragma unroll
                for (int nf = 0; nf < 2; nf++)
                    mma_f16(acc[mf][nf], a[mf][0], a[mf][1], a[mf][2], a[mf][3],
                            bh[nf][0], bh[nf][1]);
        }
        if (s + 1 < NS) STS_F((s + 1) & 1);
        if (s + 2 < NS) LDG_F(s + 2);
        __syncthreads();
    }
#undef LDG_F
#undef STS_F
#undef RL

#pragma unroll
    for (int mf = 0; mf < 4; mf++)
#pragma unroll
        for (int nf = 0; nf < 2; nf++) {
            int row = m0 + wM * 64 + mf * 16 + g;
            int col = n0 + wN * 16 + nf * 8 + t * 2;
            float b0v = (kz == 0) ? bias[col] : 0.f;
            float b1v = (kz == 0) ? bias[col + 1] : 0.f;
            float v0 = acc[mf][nf][0] + b0v, v1 = acc[mf][nf][1] + b1v;
            float v2 = acc[mf][nf][2] + b0v, v3 = acc[mf][nf][3] + b1v;
            float* p0 = &C[(long)row * N + col];
            float* p1 = &C[(long)(row + 8) * N + col];
            if (atomic) {
                atomicAdd(p0, v0); atomicAdd(p0 + 1, v1);
                atomicAdd(p1, v2); atomicAdd(p1 + 1, v3);
            } else {
                p0[0] = v0; p0[1] = v1;
                p1[0] = v2; p1[1] = v3;
            }
        }
}

// -------- GRU gates -> h_new (sums K-slice pairs), float4-vectorized ------
__global__ __launch_bounds__(256) void gru_kernel(const float* __restrict__ hidden,
                                                  float* __restrict__ out) {
    int i4 = blockIdx.x * 256 + threadIdx.x;
    if (i4 < Bb) g_expsum[i4] = 0.f;
    int e = i4 * 4;
    int b = e >> 10, j = e & 1023;
    long base = (long)b * 3 * Hh + j;
    const float4* gi  = reinterpret_cast<const float4*>(&g_gi[base]);
    const float4* gi2 = reinterpret_cast<const float4*>(&g_gi2[base]);
    const float4* gh  = reinterpret_cast<const float4*>(&g_gh[base]);
    const float4* gh2 = reinterpret_cast<const float4*>(&g_gh2[base]);
    float4 ir_a = gi[0],  iz_a = gi[Hh / 4],  in_a = gi[2 * Hh / 4];
    float4 ir_b = gi2[0], iz_b = gi2[Hh / 4], in_b = gi2[2 * Hh / 4];
    float4 hr_a = gh[0],  hz_a = gh[Hh / 4],  hn_a = gh[2 * Hh / 4];
    float4 hr_b = gh2[0], hz_b = gh2[Hh / 4], hn_b = gh2[2 * Hh / 4];
    float4 h = *reinterpret_cast<const float4*>(&hidden[e]);

    float4 o;
#pragma unroll
    for (int q = 0; q < 4; q++) {
        float irq = (&ir_a.x)[q] + (&ir_b.x)[q];
        float izq = (&iz_a.x)[q] + (&iz_b.x)[q];
        float inq = (&in_a.x)[q] + (&in_b.x)[q];
        float hrq = (&hr_a.x)[q] + (&hr_b.x)[q];
        float hzq = (&hz_a.x)[q] + (&hz_b.x)[q];
        float hnq = (&hn_a.x)[q] + (&hn_b.x)[q];
        float hq = (&h.x)[q];
        float r = 1.f / (1.f + __expf(-(irq + hrq)));
        float z = 1.f / (1.f + __expf(-(izq + hzq)));
        float n = tanhf(inq + r * hnq);
        (&o.x)[q] = (1.f - z) * n + z * hq;
    }
    *reinterpret_cast<float4*>(&out[(long)Bb * Vv + e]) = o;
    uint2 hb;
    hb.x = pack_bf2(o.x, o.y);
    hb.y = pack_bf2(o.z, o.w);
    *reinterpret_cast<uint2*>(&g_hnbf[e]) = hb;
}

// ======== big GEMM: logits = h_new @ out_W^T + out_b (+ partial expsum) ====
#define BIG_NS 32
#define A_STAGE 10240
#define B_STAGE 10240
#define B_OFF   (3 * A_STAGE)
#define BIG_SMEM (3 * A_STAGE + 2 * B_STAGE)

__global__ __launch_bounds__(256, 2) void gemm_big2(
    const __nv_bfloat16* __restrict__ Abf, const float* __restrict__ W,
    const float* __restrict__ ob, float* __restrict__ out) {
    extern __shared__ char dsm[];
    uint32_t dyn = smem_u32(dsm);

    const int tid = threadIdx.x, wid = tid >> 5, lane = tid & 31;
    const int wM = wid & 1, wN = wid >> 1;
    const int g = lane >> 2, t = lane & 3;
    const int m0 = blockIdx.x * 128;
    const long n0 = (long)blockIdx.y * 128;

    const int arow = tid >> 1, aq = (tid & 1) * 2;
    const int brow = tid >> 1, bh = tid & 1;
    const long bn = n0 + brow;
    const bool bok = bn < Vv;
    const __nv_bfloat16* asrc_base = Abf + (long)(m0 + arow) * Hh + aq * 8;
    const float* bsrc_base = W + bn * Hh + bh * 16;

    float acc[4][4][4];
#pragma unroll
    for (int i = 0; i < 4; i++)
#pragma unroll
        for (int j = 0; j < 4; j++)
#pragma unroll
            for (int q = 0; q < 4; q++) acc[i][j][q] = 0.f;

    float4 rb[4];

#define LDG_B(s)                                                              \
    if (bok) {                                                                \
        const float4* p = reinterpret_cast<const float4*>(bsrc_base + (s) * 32); \
        rb[0] = p[0]; rb[1] = p[1]; rb[2] = p[2]; rb[3] = p[3];               \
    } else {                                                                  \
        rb[0] = rb[1] = rb[2] = rb[3] = make_float4(0.f, 0.f, 0.f, 0.f);      \
    }

#define STS_B(buf)                                                            \
    {                                                                         \
        uint32_t bb = dyn + B_OFF + (buf) * B_STAGE + brow * 80 + bh * 32;    \
        uint4 u0, u1;                                                         \
        u0.x = pack_bf2(rb[0].x, rb[0].y); u0.y = pack_bf2(rb[0].z, rb[0].w); \
        u0.z = pack_bf2(rb[1].x, rb[1].y); u0.w = pack_bf2(rb[1].z, rb[1].w); \
        u1.x = pack_bf2(rb[2].x, rb[2].y); u1.y = pack_bf2(rb[2].z, rb[2].w); \
        u1.z = pack_bf2(rb[3].x, rb[3].y); u1.w = pack_bf2(rb[3].z, rb[3].w); \
        sts128(bb, u0); sts128(bb + 16, u1);                                  \
    }

#define CPA_A(s)                                                              \
    {                                                                         \
        uint32_t ab = dyn + ((s) % 3) * A_STAGE + arow * 80 + aq * 16;        \
        const __nv_bfloat16* sp = asrc_base + (s) * 32;                       \
        CP_ASYNC16(ab, sp);                                                   \
        CP_ASYNC16(ab + 16, sp + 8);                                          \
    }

    LDG_B(0); STS_B(0);
    CPA_A(0); CP_COMMIT();
    CPA_A(1); CP_COMMIT();
    LDG_B(1);
    CP_WAIT(1);
    __syncthreads();

    for (int s = 0; s < BIG_NS; s++) {
        if (s + 2 < BIG_NS) { CPA_A(s + 2); CP_COMMIT(); }

        uint32_t ab = dyn + (s % 3) * A_STAGE;
        uint32_t bb = dyn + B_OFF + (s % 2) * B_STAGE;
        int l15 = lane & 15, l16 = (lane >> 4) * 16;
#pragma unroll
        for (int kf = 0; kf < 2; kf++) {
            unsigned a[4][4], b[4][2];
#pragma unroll
            for (int mf = 0; mf < 4; mf++)
                ldm_x4(a[mf], ab + (wM * 64 + mf * 16 + l15) * 80 + kf * 32 + l16);
#pragma unroll
            for (int pr = 0; pr < 2; pr++) {
                unsigned r[4];
                ldm_x4(r, bb + (wN * 32 + pr * 16 + l15) * 80 + kf * 32 + l16);
                b[pr * 2][0] = r[0]; b[pr * 2][1] = r[2];
                b[pr * 2 + 1][0] = r[1]; b[pr * 2 + 1][1] = r[3];
            }
#pragma unroll
            for (int mf = 0; mf < 4; mf++)
#pragma unroll
                for (int nf = 0; nf < 4; nf++)
                    mma_bf16(acc[mf][nf], a[mf][0], a[mf][1], a[mf][2], a[mf][3],
                             b[nf][0], b[nf][1]);
        }

        if (s + 1 < BIG_NS) STS_B((s + 1) & 1);
        if (s + 2 < BIG_NS) { LDG_B(s + 2); CP_WAIT(1); }
        else                { CP_WAIT(0); }
        __syncthreads();
    }
#undef LDG_B
#undef STS_B
#undef CPA_A

#pragma unroll
    for (int mf = 0; mf < 4; mf++) {
        int m = m0 + wM * 64 + mf * 16 + g;
        float s0 = 0.f, s1 = 0.f;
#pragma unroll
        for (int nf = 0; nf < 4; nf++) {
            long col = n0 + wN * 32 + nf * 8 + 2 * t;
            if (col < Vv) {
                float b0 = ob[col];
                float v0 = acc[mf][nf][0] + b0;
                float v2 = acc[mf][nf][2] + b0;
                out[(long)m * Vv + col] = v0;
                out[(long)(m + 8) * Vv + col] = v2;
                s0 += __expf(v0); s1 += __expf(v2);
            }
            if (col + 1 < Vv) {
                float b1 = ob[col + 1];
                float v1 = acc[mf][nf][1] + b1;
                float v3 = acc[mf][nf][3] + b1;
                out[(long)m * Vv + col + 1] = v1;
                out[(long)(m + 8) * Vv + col + 1] = v3;
                s0 += __expf(v1); s1 += __expf(v3);
            }
        }
        s0 += __shfl_xor_sync(0xffffffffu, s0, 1);
        s0 += __shfl_xor_sync(0xffffffffu, s0, 2);
        s1 += __shfl_xor_sync(0xffffffffu, s1, 1);
        s1 += __shfl_xor_sync(0xffffffffu, s1, 2);
        if (t == 0) {
            atomicAdd(&g_expsum[m], s0);
            atomicAdd(&g_expsum[m + 8], s1);
        }
    }
}

// -------- log_softmax subtract: flat float4 pass over the logit block -----
#define E_TOT ((long)Bb * Vv)            // 12,865,792 (divisible by 4)
#define F_TOT (E_TOT / 4)                // float4 count
#define LSE_BLOCKS ((int)((F_TOT + 255) / 256))

__global__ __launch_bounds__(256) void lse_sub(float* __restrict__ out) {
    const long f0 = (long)blockIdx.x * 256;
    const int tid = threadIdx.x;
    __shared__ float slse[2];
    __shared__ int srow0;
    if (tid == 0) {
        int r0 = (int)((f0 * 4) / Vv);
        srow0 = r0;
        slse[0] = logf(g_expsum[r0]);
        long e_last = (f0 + 256) * 4 - 1;
        if (e_last > E_TOT - 1) e_last = E_TOT - 1;
        int r1 = (int)(e_last / Vv);
        slse[1] = (r1 > r0) ? logf(g_expsum[r1]) : slse[0];
    }
    __syncthreads();
    long f = f0 + tid;
    if (f >= F_TOT) return;
    float4 v = reinterpret_cast<float4*>(out)[f];
    long e = f * 4;
    long boundary = (long)(srow0 + 1) * Vv;   // first element of next row
    float l0 = slse[0], l1 = slse[1];
    v.x -= (e + 0 >= boundary) ? l1 : l0;
    v.y -= (e + 1 >= boundary) ? l1 : l0;
    v.z -= (e + 2 >= boundary) ? l1 : l0;
    v.w -= (e + 3 >= boundary) ? l1 : l0;
    reinterpret_cast<float4*>(out)[f] = v;
}

// -------- launch ----------
extern "C" void kernel_launch(void* const* d_in, const int* in_sizes, int n_in,
                              void* d_out, int out_size) {
    const int*   tokens = (const int*)d_in[0];
    const float* hidden = (const float*)d_in[1];
    const float* enc    = (const float*)d_in[2];
    const float* emb    = (const float*)d_in[3];
    const float* attn_W = (const float*)d_in[4];
    const float* attn_b = (const float*)d_in[5];
    const float* comb_W = (const float*)d_in[6];
    const float* comb_b = (const float*)d_in[7];
    const float* W_ih   = (const float*)d_in[8];
    const float* W_hh   = (const float*)d_in[9];
    const float* b_ih   = (const float*)d_in[10];
    const float* b_hh   = (const float*)d_in[11];
    const float* out_W  = (const float*)d_in[12];
    const float* out_b  = (const float*)d_in[13];
    float* out = (float*)d_out;

    float *p_xin, *p_x, *p_gi, *p_gi2, *p_gh, *p_gh2;
    __nv_bfloat16* p_hn;
    cudaGetSymbolAddress((void**)&p_xin, g_xin);
    cudaGetSymbolAddress((void**)&p_x,   g_x);
    cudaGetSymbolAddress((void**)&p_gi,  g_gi);
    cudaGetSymbolAddress((void**)&p_gi2, g_gi2);
    cudaGetSymbolAddress((void**)&p_gh,  g_gh);
    cudaGetSymbolAddress((void**)&p_gh2, g_gh2);
    cudaGetSymbolAddress((void**)&p_hn,  g_hnbf);

    static int smem_set = 0;
    if (!smem_set) {
        cudaFuncSetAttribute(gemm_big2, cudaFuncAttributeMaxDynamicSharedMemorySize, BIG_SMEM);
        smem_set = 1;
    }

    attn_kernel<<<Bb, 256>>>(tokens, hidden, enc, emb, attn_W, attn_b, out);

    // combine: split-K=8, atomic accumulate into zeroed g_x (relu deferred)
    dim3 gc(1024 / 64, 256 / 128, 8);
    gemm_front2<<<gc, 256>>>(p_xin, comb_W, comb_b, p_x, p_x, 0,
                             p_xin, comb_W, comb_b, p_x, p_x, 0,
                             1024, 2048, 0);

    // gates: gi = relu(g_x) @ W_ih^T (slices -> g_gi/g_gi2),
    //        gh = hidden @ W_hh^T    (slices -> g_gh/g_gh2)
    dim3 gg(3072 / 64, 256 / 128, 4);
    gemm_front2<<<gg, 256>>>(p_x, W_ih, b_ih, p_gi, p_gi2, 1,
                             hidden, W_hh, b_hh, p_gh, p_gh2, 0,
                             3072, 1024, 1);

    gru_kernel<<<(Bb * Hh) / 1024, 256>>>(hidden, out);

    dim3 gb(2, (Vv + 127) / 128);
    gemm_big2<<<gb, 256, BIG_SMEM>>>(p_hn, out_W, out_b, out);

    lse_sub<<<LSE_BLOCKS, 256>>>(out);
}